// round 2
// baseline (speedup 1.0000x reference)
#include <cuda_runtime.h>
#include <math.h>

#define B_  4
#define Nn  384
#define E_  768
#define H_  32
#define F_  3072
#define L_  12
#define S_  512
#define D_  24
#define T_  (B_*Nn)          // 1536 tokens

// -------------------- scratch (static device allocations) --------------------
__device__ float g_x   [T_*E_];
__device__ float g_q   [T_*E_];
__device__ float g_k   [T_*E_];
__device__ float g_v   [T_*E_];
__device__ float g_h   [T_*F_];
__device__ float g_bias[B_*H_*Nn*Nn];
__device__ float g_sc  [B_*H_*Nn*Nn];

// -------------------- embedding: x[n*B+b][e] --------------------
__global__ void embed_k(const int* __restrict__ nt, const float* __restrict__ nif,
                        const int* __restrict__ ind, const int* __restrict__ outd,
                        const float* __restrict__ nemb, const float* __restrict__ iemb,
                        const float* __restrict__ oemb, float* __restrict__ x) {
    int idx = blockIdx.x * blockDim.x + threadIdx.x;
    if (idx >= T_*E_) return;
    int e = idx % E_, tok = idx / E_;
    int b = tok % B_, n = tok / B_;
    int bn = b*Nn + n;
    int t  = nt[bn];
    x[idx] = nemb[t*E_+e] + iemb[ind[bn]*E_+e] + oemb[outd[bn]*E_+e] + nif[(size_t)bn*E_+e];
}

// -------------------- spatial bias: bias[b,h,n,m] --------------------
__global__ void bias_k(const int* __restrict__ sp, const float* __restrict__ ab,
                       const float* __restrict__ se, const float* __restrict__ ser,
                       float* __restrict__ bias) {
    long idx = (long)blockIdx.x * blockDim.x + threadIdx.x;
    if (idx >= (long)B_*H_*Nn*Nn) return;
    int m = (int)(idx % Nn); long r = idx / Nn;
    int n = (int)(r % Nn);   r /= Nn;
    int h = (int)(r % H_);
    int b = (int)(r / H_);
    int s1 = sp[(b*Nn+n)*Nn + m];
    int s2 = sp[(b*Nn+m)*Nn + n];
    bias[idx] = se[s1*H_+h] + ser[s2*H_+h] + ab[(b*Nn+n)*Nn + m];
}

// -------------------- SGEMM: C[M,Nc] = epi((A[M,K]@W[K,Nc] + bias) * scale) ----
// 64x64 tile, BK=16, 256 threads, 4x4 per thread. M,Nc % 64 == 0, K % 16 == 0.
__device__ __forceinline__ float gelu_f(float x) {
    return 0.5f * x * (1.0f + tanhf(0.7978845608028654f * (x + 0.044715f * x * x * x)));
}

template<int EPI>  // 0 = bias(+scale), 1 = bias + gelu
__global__ void __launch_bounds__(256)
sgemm_k(const float* __restrict__ A, const float* __restrict__ W,
        const float* __restrict__ bias, float* __restrict__ C,
        int M, int K, int Nc, float scale) {
    __shared__ float As[16][64];
    __shared__ float Bs[16][64];
    int tid = threadIdx.x;
    int bx = blockIdx.x, by = blockIdx.y;
    int tx = tid & 15, ty = tid >> 4;
    float acc[4][4] = {};

    int a_row = tid >> 2;            // 0..63
    int a_col = (tid & 3) << 2;      // 0,4,8,12
    int b_row = tid >> 4;            // 0..15
    int b_col = (tid & 15) << 2;     // 0..60
    const float* Aptr = A + (size_t)(by*64 + a_row) * K + a_col;
    const float* Wptr = W + (size_t)b_row * Nc + bx*64 + b_col;

    for (int k0 = 0; k0 < K; k0 += 16) {
        float4 av = *(const float4*)(Aptr + k0);
        As[a_col+0][a_row] = av.x;
        As[a_col+1][a_row] = av.y;
        As[a_col+2][a_row] = av.z;
        As[a_col+3][a_row] = av.w;
        float4 bv = *(const float4*)(Wptr + (size_t)k0 * Nc);
        *(float4*)&Bs[b_row][b_col] = bv;
        __syncthreads();
#pragma unroll
        for (int kk = 0; kk < 16; kk++) {
            float4 ra = *(const float4*)&As[kk][ty << 2];
            float4 rb = *(const float4*)&Bs[kk][tx << 2];
            acc[0][0] += ra.x*rb.x; acc[0][1] += ra.x*rb.y; acc[0][2] += ra.x*rb.z; acc[0][3] += ra.x*rb.w;
            acc[1][0] += ra.y*rb.x; acc[1][1] += ra.y*rb.y; acc[1][2] += ra.y*rb.z; acc[1][3] += ra.y*rb.w;
            acc[2][0] += ra.z*rb.x; acc[2][1] += ra.z*rb.y; acc[2][2] += ra.z*rb.z; acc[2][3] += ra.z*rb.w;
            acc[3][0] += ra.w*rb.x; acc[3][1] += ra.w*rb.y; acc[3][2] += ra.w*rb.z; acc[3][3] += ra.w*rb.w;
        }
        __syncthreads();
    }

    int row0 = by*64 + (ty << 2);
    int col0 = bx*64 + (tx << 2);
    float b0 = bias[col0], b1 = bias[col0+1], b2 = bias[col0+2], b3 = bias[col0+3];
#pragma unroll
    for (int i = 0; i < 4; i++) {
        float4 o;
        o.x = (acc[i][0] + b0) * scale;
        o.y = (acc[i][1] + b1) * scale;
        o.z = (acc[i][2] + b2) * scale;
        o.w = (acc[i][3] + b3) * scale;
        if (EPI == 1) { o.x = gelu_f(o.x); o.y = gelu_f(o.y); o.z = gelu_f(o.z); o.w = gelu_f(o.w); }
        *(float4*)&C[(size_t)(row0 + i) * Nc + col0] = o;
    }
}

// -------------------- attention scores: sc[b,h,n,m] = q.k + bias --------------
__global__ void __launch_bounds__(256)
scores_k(const float* __restrict__ q, const float* __restrict__ k,
         const float* __restrict__ bias, float* __restrict__ sc) {
    int bh = blockIdx.x;                 // b*H + h
    int b = bh / H_, h = bh % H_;
    int n0 = blockIdx.y * 32, m0 = blockIdx.z * 32;
    __shared__ float Qs[32][25], Ks[32][25];
    int tid = threadIdx.x;
    for (int i = tid; i < 32*24; i += 256) {
        int r = i / 24, d = i % 24;
        Qs[r][d] = q[((size_t)(n0+r)*B_ + b)*E_ + h*D_ + d];
        Ks[r][d] = k[((size_t)(m0+r)*B_ + b)*E_ + h*D_ + d];
    }
    __syncthreads();
    int tx = tid & 31, ty = tid >> 5;    // ty 0..7
    int base = (bh*Nn + n0) * Nn;
#pragma unroll
    for (int i = 0; i < 4; i++) {
        int nl = (ty << 2) + i;
        float acc = 0.f;
#pragma unroll
        for (int d = 0; d < 24; d++) acc += Qs[nl][d] * Ks[tx][d];
        int o = base + nl*Nn + m0 + tx;
        sc[o] = acc + bias[o];
    }
}

// -------------------- softmax over last dim (Nn=384), in place ----------------
__global__ void __launch_bounds__(128)
softmax_k(float* __restrict__ sc, const int* __restrict__ nt) {
    int row = blockIdx.x;                // bh*Nn + n
    int b = row / (H_*Nn);
    float* p = sc + (size_t)row * Nn;
    int tid = threadIdx.x;
    float vv[3]; float mx = -3.4e38f;
#pragma unroll
    for (int i = 0; i < 3; i++) {
        int m = tid + (i << 7);
        float val = p[m];
        if (nt[b*Nn + m] == 0) val = __int_as_float(0xff800000); // -inf (padding mask)
        vv[i] = val; mx = fmaxf(mx, val);
    }
    __shared__ float r1[4], r2[4];
    for (int o = 16; o; o >>= 1) mx = fmaxf(mx, __shfl_xor_sync(0xffffffffu, mx, o));
    if ((tid & 31) == 0) r1[tid >> 5] = mx;
    __syncthreads();
    mx = fmaxf(fmaxf(r1[0], r1[1]), fmaxf(r1[2], r1[3]));
    float sum = 0.f;
#pragma unroll
    for (int i = 0; i < 3; i++) { vv[i] = __expf(vv[i] - mx); sum += vv[i]; }
    for (int o = 16; o; o >>= 1) sum += __shfl_xor_sync(0xffffffffu, sum, o);
    if ((tid & 31) == 0) r2[tid >> 5] = sum;
    __syncthreads();
    sum = r2[0] + r2[1] + r2[2] + r2[3];
    float inv = 1.f / sum;
#pragma unroll
    for (int i = 0; i < 3; i++) p[tid + (i << 7)] = vv[i] * inv;
}

// -------------------- PV: out[n,b,h,d] = sum_m P[b,h,n,m] * v[m,b,h,d] --------
__global__ void __launch_bounds__(256)
pv_k(const float* __restrict__ sc, const float* __restrict__ v, float* __restrict__ out) {
    int bh = blockIdx.x; int b = bh / H_, h = bh % H_;
    int n0 = blockIdx.y * 32;
    __shared__ float Ps[32][64];
    __shared__ float Vs[64][25];
    int tid = threadIdx.x;
    float acc[3] = {0.f, 0.f, 0.f};
    for (int mt = 0; mt < Nn; mt += 64) {
        for (int i = tid; i < 32*64; i += 256) {
            int r = i >> 6, c = i & 63;
            Ps[r][c] = sc[(bh*Nn + n0 + r)*Nn + mt + c];
        }
        for (int i = tid; i < 64*24; i += 256) {
            int r = i / 24, d = i % 24;
            Vs[r][d] = v[((size_t)(mt+r)*B_ + b)*E_ + h*D_ + d];
        }
        __syncthreads();
#pragma unroll
        for (int j = 0; j < 3; j++) {
            int o = tid + (j << 8);
            int nl = o / 24, d = o % 24;
            float a = 0.f;
#pragma unroll
            for (int m = 0; m < 64; m++) a += Ps[nl][m] * Vs[m][d];
            acc[j] += a;
        }
        __syncthreads();
    }
#pragma unroll
    for (int j = 0; j < 3; j++) {
        int o = tid + (j << 8);
        int nl = o / 24, d = o % 24;
        out[((size_t)(n0+nl)*B_ + b)*E_ + h*D_ + d] = acc[j];
    }
}

// -------------------- residual add + LayerNorm --------------------
__global__ void __launch_bounds__(256)
ln_k(const float* __restrict__ x, const float* __restrict__ a,
     const float* __restrict__ s, const float* __restrict__ bb, float* __restrict__ out) {
    __shared__ float r1[8], r2[8];
    int t = blockIdx.x, tid = threadIdx.x;
    const float* xp = x + (size_t)t * E_;
    const float* ap = a + (size_t)t * E_;
    float v[3]; float sum = 0.f;
#pragma unroll
    for (int i = 0; i < 3; i++) { int e = tid + (i << 8); v[i] = xp[e] + ap[e]; sum += v[i]; }
    for (int o = 16; o; o >>= 1) sum += __shfl_xor_sync(0xffffffffu, sum, o);
    if ((tid & 31) == 0) r1[tid >> 5] = sum;
    __syncthreads();
    sum = 0.f;
#pragma unroll
    for (int w = 0; w < 8; w++) sum += r1[w];
    float mu = sum * (1.f / 768.f);
    float var = 0.f;
#pragma unroll
    for (int i = 0; i < 3; i++) { float d = v[i] - mu; var += d * d; }
    for (int o = 16; o; o >>= 1) var += __shfl_xor_sync(0xffffffffu, var, o);
    if ((tid & 31) == 0) r2[tid >> 5] = var;
    __syncthreads();
    var = 0.f;
#pragma unroll
    for (int w = 0; w < 8; w++) var += r2[w];
    float rstd = rsqrtf(var * (1.f / 768.f) + 1e-5f);
    float* op = out + (size_t)t * E_;
#pragma unroll
    for (int i = 0; i < 3; i++) {
        int e = tid + (i << 8);
        op[e] = (v[i] - mu) * rstd * s[e] + bb[e];
    }
}

// -------------------- orchestration --------------------
extern "C" void kernel_launch(void* const* d_in, const int* in_sizes, int n_in,
                              void* d_out, int out_size) {
    const int*   nt    = (const int*)  d_in[0];
    const float* nif   = (const float*)d_in[1];
    const int*   ind   = (const int*)  d_in[2];
    const int*   outd  = (const int*)  d_in[3];
    const float* ab    = (const float*)d_in[4];
    const int*   sp    = (const int*)  d_in[5];
    const float* nemb  = (const float*)d_in[6];
    const float* iemb  = (const float*)d_in[7];
    const float* oemb  = (const float*)d_in[8];
    const float* se    = (const float*)d_in[9];
    const float* ser   = (const float*)d_in[10];
    const float* Wq    = (const float*)d_in[11];
    const float* bq    = (const float*)d_in[12];
    const float* Wk    = (const float*)d_in[13];
    const float* bk    = (const float*)d_in[14];
    const float* Wv    = (const float*)d_in[15];
    const float* bv    = (const float*)d_in[16];
    const float* Wo    = (const float*)d_in[17];
    const float* bo    = (const float*)d_in[18];
    const float* W1    = (const float*)d_in[19];
    const float* b1    = (const float*)d_in[20];
    const float* W2    = (const float*)d_in[21];
    const float* b2    = (const float*)d_in[22];
    const float* ln1s  = (const float*)d_in[23];
    const float* ln1b  = (const float*)d_in[24];
    const float* ln2s  = (const float*)d_in[25];
    const float* ln2b  = (const float*)d_in[26];
    float* out = (float*)d_out;

    float *x, *q, *k, *v, *h, *bias, *sc;
    cudaGetSymbolAddress((void**)&x,    g_x);
    cudaGetSymbolAddress((void**)&q,    g_q);
    cudaGetSymbolAddress((void**)&k,    g_k);
    cudaGetSymbolAddress((void**)&v,    g_v);
    cudaGetSymbolAddress((void**)&h,    g_h);
    cudaGetSymbolAddress((void**)&bias, g_bias);
    cudaGetSymbolAddress((void**)&sc,   g_sc);

    embed_k<<<(T_*E_ + 255)/256, 256>>>(nt, nif, ind, outd, nemb, iemb, oemb, x);
    long btot = (long)B_*H_*Nn*Nn;
    bias_k<<<(unsigned)((btot + 255)/256), 256>>>(sp, ab, se, ser, bias);

    const float scaling = 0.20412414523193154f;   // 24^-0.5
    dim3 gE(E_/64, T_/64);        // (12, 24)
    dim3 gF(F_/64, T_/64);        // (48, 24)
    dim3 gs(B_*H_, Nn/32, Nn/32); // (128, 12, 12)
    dim3 gpv(B_*H_, Nn/32);       // (128, 12)

    for (int l = 0; l < L_; l++) {
        const float* wq = Wq + (size_t)l*E_*E_;
        const float* wk = Wk + (size_t)l*E_*E_;
        const float* wv = Wv + (size_t)l*E_*E_;
        const float* wo = Wo + (size_t)l*E_*E_;
        const float* w1 = W1 + (size_t)l*E_*F_;
        const float* w2 = W2 + (size_t)l*F_*E_;

        sgemm_k<0><<<gE, 256>>>(x, wq, bq + l*E_, q, T_, E_, E_, scaling);
        sgemm_k<0><<<gE, 256>>>(x, wk, bk + l*E_, k, T_, E_, E_, 1.f);
        sgemm_k<0><<<gE, 256>>>(x, wv, bv + l*E_, v, T_, E_, E_, 1.f);

        scores_k<<<gs, 256>>>(q, k, bias, sc);
        softmax_k<<<B_*H_*Nn, 128>>>(sc, nt);
        pv_k<<<gpv, 256>>>(sc, v, q);                       // q := attention context

        sgemm_k<0><<<gE, 256>>>(q, wo, bo + l*E_, k, T_, E_, E_, 1.f);  // k := O-proj
        ln_k<<<T_, 256>>>(x, k, ln1s + l*E_, ln1b + l*E_, x);

        sgemm_k<1><<<gF, 256>>>(x, w1, b1 + l*F_, h, T_, E_, F_, 1.f);  // gelu fused
        sgemm_k<0><<<gE, 256>>>(h, w2, b2 + l*E_, q, T_, F_, E_, 1.f);  // q := FFN out

        float* dst = (l == L_-1) ? out : x;
        ln_k<<<T_, 256>>>(x, q, ln2s + l*E_, ln2b + l*E_, dst);
    }
}

// round 3
// speedup vs baseline: 1.5483x; 1.5483x over previous
#include <cuda_runtime.h>
#include <math.h>

#define B_  4
#define Nn  384
#define E_  768
#define H_  32
#define F_  3072
#define L_  12
#define S_  512
#define D_  24
#define T_  (B_*Nn)          // 1536 tokens

// -------------------- scratch (static device allocations) --------------------
__device__ float g_x   [T_*E_];
__device__ float g_q   [T_*E_];
__device__ float g_k   [T_*E_];
__device__ float g_v   [T_*E_];
__device__ float g_h   [T_*F_];
__device__ float g_bias[B_*H_*Nn*Nn];
__device__ float g_sc  [B_*H_*Nn*Nn];

// -------------------- embedding: x[n*B+b][e] --------------------
__global__ void embed_k(const int* __restrict__ nt, const float* __restrict__ nif,
                        const int* __restrict__ ind, const int* __restrict__ outd,
                        const float* __restrict__ nemb, const float* __restrict__ iemb,
                        const float* __restrict__ oemb, float* __restrict__ x) {
    int idx = blockIdx.x * blockDim.x + threadIdx.x;
    if (idx >= T_*E_) return;
    int e = idx % E_, tok = idx / E_;
    int b = tok % B_, n = tok / B_;
    int bn = b*Nn + n;
    int t  = nt[bn];
    x[idx] = nemb[t*E_+e] + iemb[ind[bn]*E_+e] + oemb[outd[bn]*E_+e] + nif[(size_t)bn*E_+e];
}

// -------------------- spatial bias: bias[b,h,n,m] --------------------
__global__ void bias_k(const int* __restrict__ sp, const float* __restrict__ ab,
                       const float* __restrict__ se, const float* __restrict__ ser,
                       float* __restrict__ bias) {
    long idx = (long)blockIdx.x * blockDim.x + threadIdx.x;
    if (idx >= (long)B_*H_*Nn*Nn) return;
    int m = (int)(idx % Nn); long r = idx / Nn;
    int n = (int)(r % Nn);   r /= Nn;
    int h = (int)(r % H_);
    int b = (int)(r / H_);
    int s1 = sp[(b*Nn+n)*Nn + m];
    int s2 = sp[(b*Nn+m)*Nn + n];
    bias[idx] = se[s1*H_+h] + ser[s2*H_+h] + ab[(b*Nn+n)*Nn + m];
}

__device__ __forceinline__ float gelu_f(float x) {
    return 0.5f * x * (1.0f + tanhf(0.7978845608028654f * (x + 0.044715f * x * x * x)));
}

__device__ __forceinline__ unsigned cvt_tf32(float x) {
    unsigned r; asm("cvt.rna.tf32.f32 %0, %1;" : "=r"(r) : "f"(x)); return r;
}

// -------------------- tensor-core GEMM (tf32 mma.sync) --------------------
// C[M,Nc] = epi((A[M,K]@W[K,Nc] + bias) * scale)
// Block tile 128x64, BK=16, 256 threads = 8 warps (4m x 2n), warp tile 32x32.
// Requires M%128==0, Nc%64==0, K%16==0.
#define BM 128
#define BN 64
#define BKK 16

template<int EPI>  // 0 = bias(+scale), 1 = bias + gelu
__global__ void __launch_bounds__(256)
tgemm_k(const float* __restrict__ A, const float* __restrict__ W,
        const float* __restrict__ bias, float* __restrict__ C,
        int M, int K, int Nc, float scale) {
    __shared__ unsigned As[2][BM][20];   // tf32 bits, [m][k], stride 20 (conflict-free frag LDS)
    __shared__ unsigned Bs[2][BKK][BN];  // [k][n], col swizzled: n ^ (8*(k&3))

    int tid  = threadIdx.x;
    int wid  = tid >> 5, lane = tid & 31;
    int g    = lane >> 2;        // groupID 0..7
    int q    = lane & 3;         // thread-in-group 0..3
    int wm   = (wid & 3) * 32;   // warp m offset in block tile
    int wn   = (wid >> 2) * 32;  // warp n offset
    int bm0  = blockIdx.y * BM;
    int bn0  = blockIdx.x * BN;

    // global load mapping
    int am = tid >> 1;           // 0..127 (A row within tile)
    int ak = (tid & 1) * 8;      // 0 or 8 (A k offset)
    int bk = tid >> 4;           // 0..15  (B k row)
    int bn = (tid & 15) * 4;     // 0..60  (B n offset)
    const float* Ap = A + (size_t)(bm0 + am) * K + ak;
    const float* Wp = W + (size_t)bk * Nc + bn0 + bn;
    int sn = bn ^ (8 * (bk & 3));  // swizzled B column base

    float acc[2][4][4];
#pragma unroll
    for (int i = 0; i < 2; i++)
#pragma unroll
        for (int j = 0; j < 4; j++)
#pragma unroll
            for (int c = 0; c < 4; c++) acc[i][j][c] = 0.f;

    // prologue: load tile 0
    float4 ra0 = *(const float4*)(Ap);
    float4 ra1 = *(const float4*)(Ap + 4);
    float4 rb0 = *(const float4*)(Wp);
    {
        As[0][am][ak+0] = cvt_tf32(ra0.x); As[0][am][ak+1] = cvt_tf32(ra0.y);
        As[0][am][ak+2] = cvt_tf32(ra0.z); As[0][am][ak+3] = cvt_tf32(ra0.w);
        As[0][am][ak+4] = cvt_tf32(ra1.x); As[0][am][ak+5] = cvt_tf32(ra1.y);
        As[0][am][ak+6] = cvt_tf32(ra1.z); As[0][am][ak+7] = cvt_tf32(ra1.w);
        Bs[0][bk][sn+0] = cvt_tf32(rb0.x); Bs[0][bk][sn+1] = cvt_tf32(rb0.y);
        Bs[0][bk][sn+2] = cvt_tf32(rb0.z); Bs[0][bk][sn+3] = cvt_tf32(rb0.w);
    }
    __syncthreads();

    int ntiles = K / BKK;
    int s = 0;
    for (int t = 0; t < ntiles; t++) {
        // prefetch next tile into registers (latency overlapped with mma)
        if (t + 1 < ntiles) {
            const float* Ap2 = Ap + (size_t)(t + 1) * BKK;
            const float* Wp2 = Wp + (size_t)(t + 1) * BKK * Nc;
            ra0 = *(const float4*)(Ap2);
            ra1 = *(const float4*)(Ap2 + 4);
            rb0 = *(const float4*)(Wp2);
        }
        // compute on stage s
#pragma unroll
        for (int kk = 0; kk < 2; kk++) {
            int k0 = kk * 8;
            unsigned af[2][4], bf[4][2];
#pragma unroll
            for (int mt = 0; mt < 2; mt++) {
                int mr = wm + mt * 16;
                af[mt][0] = As[s][mr + g    ][k0 + q];
                af[mt][1] = As[s][mr + g + 8][k0 + q];
                af[mt][2] = As[s][mr + g    ][k0 + q + 4];
                af[mt][3] = As[s][mr + g + 8][k0 + q + 4];
            }
#pragma unroll
            for (int nt2 = 0; nt2 < 4; nt2++) {
                int nc = (wn + nt2 * 8 + g) ^ (8 * q);   // swizzle: (k0+q)&3 == q
                bf[nt2][0] = Bs[s][k0 + q    ][nc];
                bf[nt2][1] = Bs[s][k0 + q + 4][nc];
            }
#pragma unroll
            for (int mt = 0; mt < 2; mt++)
#pragma unroll
                for (int nt2 = 0; nt2 < 4; nt2++)
                    asm volatile(
                        "mma.sync.aligned.m16n8k8.row.col.f32.tf32.tf32.f32 "
                        "{%0,%1,%2,%3}, {%4,%5,%6,%7}, {%8,%9}, {%0,%1,%2,%3};"
                        : "+f"(acc[mt][nt2][0]), "+f"(acc[mt][nt2][1]),
                          "+f"(acc[mt][nt2][2]), "+f"(acc[mt][nt2][3])
                        : "r"(af[mt][0]), "r"(af[mt][1]), "r"(af[mt][2]), "r"(af[mt][3]),
                          "r"(bf[nt2][0]), "r"(bf[nt2][1]));
        }
        // store next tile into stage s^1
        if (t + 1 < ntiles) {
            int s2 = s ^ 1;
            As[s2][am][ak+0] = cvt_tf32(ra0.x); As[s2][am][ak+1] = cvt_tf32(ra0.y);
            As[s2][am][ak+2] = cvt_tf32(ra0.z); As[s2][am][ak+3] = cvt_tf32(ra0.w);
            As[s2][am][ak+4] = cvt_tf32(ra1.x); As[s2][am][ak+5] = cvt_tf32(ra1.y);
            As[s2][am][ak+6] = cvt_tf32(ra1.z); As[s2][am][ak+7] = cvt_tf32(ra1.w);
            Bs[s2][bk][sn+0] = cvt_tf32(rb0.x); Bs[s2][bk][sn+1] = cvt_tf32(rb0.y);
            Bs[s2][bk][sn+2] = cvt_tf32(rb0.z); Bs[s2][bk][sn+3] = cvt_tf32(rb0.w);
        }
        __syncthreads();
        s ^= 1;
    }

    // epilogue: C fragment (g, 2q) layout
#pragma unroll
    for (int mt = 0; mt < 2; mt++) {
#pragma unroll
        for (int nt2 = 0; nt2 < 4; nt2++) {
            int col = bn0 + wn + nt2 * 8 + 2 * q;
            int r0  = bm0 + wm + mt * 16 + g;
            float blo = bias[col], bhi = bias[col + 1];
            float2 o0, o1;
            o0.x = (acc[mt][nt2][0] + blo) * scale;
            o0.y = (acc[mt][nt2][1] + bhi) * scale;
            o1.x = (acc[mt][nt2][2] + blo) * scale;
            o1.y = (acc[mt][nt2][3] + bhi) * scale;
            if (EPI == 1) {
                o0.x = gelu_f(o0.x); o0.y = gelu_f(o0.y);
                o1.x = gelu_f(o1.x); o1.y = gelu_f(o1.y);
            }
            *(float2*)&C[(size_t)r0       * Nc + col] = o0;
            *(float2*)&C[(size_t)(r0 + 8) * Nc + col] = o1;
        }
    }
}

// -------------------- attention scores: sc[b,h,n,m] = q.k + bias --------------
__global__ void __launch_bounds__(256)
scores_k(const float* __restrict__ q, const float* __restrict__ k,
         const float* __restrict__ bias, float* __restrict__ sc) {
    int bh = blockIdx.x;                 // b*H + h
    int b = bh / H_, h = bh % H_;
    int n0 = blockIdx.y * 32, m0 = blockIdx.z * 32;
    __shared__ float Qs[32][25], Ks[32][25];
    int tid = threadIdx.x;
    for (int i = tid; i < 32*24; i += 256) {
        int r = i / 24, d = i % 24;
        Qs[r][d] = q[((size_t)(n0+r)*B_ + b)*E_ + h*D_ + d];
        Ks[r][d] = k[((size_t)(m0+r)*B_ + b)*E_ + h*D_ + d];
    }
    __syncthreads();
    int tx = tid & 31, ty = tid >> 5;    // ty 0..7
    int base = (bh*Nn + n0) * Nn;
#pragma unroll
    for (int i = 0; i < 4; i++) {
        int nl = (ty << 2) + i;
        float acc = 0.f;
#pragma unroll
        for (int d = 0; d < 24; d++) acc += Qs[nl][d] * Ks[tx][d];
        int o = base + nl*Nn + m0 + tx;
        sc[o] = acc + bias[o];
    }
}

// -------------------- softmax over last dim (Nn=384), in place ----------------
__global__ void __launch_bounds__(128)
softmax_k(float* __restrict__ sc, const int* __restrict__ nt) {
    int row = blockIdx.x;                // bh*Nn + n
    int b = row / (H_*Nn);
    float* p = sc + (size_t)row * Nn;
    int tid = threadIdx.x;
    float vv[3]; float mx = -3.4e38f;
#pragma unroll
    for (int i = 0; i < 3; i++) {
        int m = tid + (i << 7);
        float val = p[m];
        if (nt[b*Nn + m] == 0) val = __int_as_float(0xff800000); // -inf (padding mask)
        vv[i] = val; mx = fmaxf(mx, val);
    }
    __shared__ float r1[4], r2[4];
    for (int o = 16; o; o >>= 1) mx = fmaxf(mx, __shfl_xor_sync(0xffffffffu, mx, o));
    if ((tid & 31) == 0) r1[tid >> 5] = mx;
    __syncthreads();
    mx = fmaxf(fmaxf(r1[0], r1[1]), fmaxf(r1[2], r1[3]));
    float sum = 0.f;
#pragma unroll
    for (int i = 0; i < 3; i++) { vv[i] = __expf(vv[i] - mx); sum += vv[i]; }
    for (int o = 16; o; o >>= 1) sum += __shfl_xor_sync(0xffffffffu, sum, o);
    if ((tid & 31) == 0) r2[tid >> 5] = sum;
    __syncthreads();
    sum = r2[0] + r2[1] + r2[2] + r2[3];
    float inv = 1.f / sum;
#pragma unroll
    for (int i = 0; i < 3; i++) p[tid + (i << 7)] = vv[i] * inv;
}

// -------------------- PV: out[n,b,h,d] = sum_m P[b,h,n,m] * v[m,b,h,d] --------
__global__ void __launch_bounds__(256)
pv_k(const float* __restrict__ sc, const float* __restrict__ v, float* __restrict__ out) {
    int bh = blockIdx.x; int b = bh / H_, h = bh % H_;
    int n0 = blockIdx.y * 32;
    __shared__ float Ps[32][64];
    __shared__ float Vs[64][25];
    int tid = threadIdx.x;
    float acc[3] = {0.f, 0.f, 0.f};
    for (int mt = 0; mt < Nn; mt += 64) {
        for (int i = tid; i < 32*64; i += 256) {
            int r = i >> 6, c = i & 63;
            Ps[r][c] = sc[(bh*Nn + n0 + r)*Nn + mt + c];
        }
        for (int i = tid; i < 64*24; i += 256) {
            int r = i / 24, d = i % 24;
            Vs[r][d] = v[((size_t)(mt+r)*B_ + b)*E_ + h*D_ + d];
        }
        __syncthreads();
#pragma unroll
        for (int j = 0; j < 3; j++) {
            int o = tid + (j << 8);
            int nl = o / 24, d = o % 24;
            float a = 0.f;
#pragma unroll
            for (int m = 0; m < 64; m++) a += Ps[nl][m] * Vs[m][d];
            acc[j] += a;
        }
        __syncthreads();
    }
#pragma unroll
    for (int j = 0; j < 3; j++) {
        int o = tid + (j << 8);
        int nl = o / 24, d = o % 24;
        out[((size_t)(n0+nl)*B_ + b)*E_ + h*D_ + d] = acc[j];
    }
}

// -------------------- residual add + LayerNorm --------------------
__global__ void __launch_bounds__(256)
ln_k(const float* __restrict__ x, const float* __restrict__ a,
     const float* __restrict__ s, const float* __restrict__ bb, float* __restrict__ out) {
    __shared__ float r1[8], r2[8];
    int t = blockIdx.x, tid = threadIdx.x;
    const float* xp = x + (size_t)t * E_;
    const float* ap = a + (size_t)t * E_;
    float v[3]; float sum = 0.f;
#pragma unroll
    for (int i = 0; i < 3; i++) { int e = tid + (i << 8); v[i] = xp[e] + ap[e]; sum += v[i]; }
    for (int o = 16; o; o >>= 1) sum += __shfl_xor_sync(0xffffffffu, sum, o);
    if ((tid & 31) == 0) r1[tid >> 5] = sum;
    __syncthreads();
    sum = 0.f;
#pragma unroll
    for (int w = 0; w < 8; w++) sum += r1[w];
    float mu = sum * (1.f / 768.f);
    float var = 0.f;
#pragma unroll
    for (int i = 0; i < 3; i++) { float d = v[i] - mu; var += d * d; }
    for (int o = 16; o; o >>= 1) var += __shfl_xor_sync(0xffffffffu, var, o);
    if ((tid & 31) == 0) r2[tid >> 5] = var;
    __syncthreads();
    var = 0.f;
#pragma unroll
    for (int w = 0; w < 8; w++) var += r2[w];
    float rstd = rsqrtf(var * (1.f / 768.f) + 1e-5f);
    float* op = out + (size_t)t * E_;
#pragma unroll
    for (int i = 0; i < 3; i++) {
        int e = tid + (i << 8);
        op[e] = (v[i] - mu) * rstd * s[e] + bb[e];
    }
}

// -------------------- orchestration --------------------
extern "C" void kernel_launch(void* const* d_in, const int* in_sizes, int n_in,
                              void* d_out, int out_size) {
    const int*   nt    = (const int*)  d_in[0];
    const float* nif   = (const float*)d_in[1];
    const int*   ind   = (const int*)  d_in[2];
    const int*   outd  = (const int*)  d_in[3];
    const float* ab    = (const float*)d_in[4];
    const int*   sp    = (const int*)  d_in[5];
    const float* nemb  = (const float*)d_in[6];
    const float* iemb  = (const float*)d_in[7];
    const float* oemb  = (const float*)d_in[8];
    const float* se    = (const float*)d_in[9];
    const float* ser   = (const float*)d_in[10];
    const float* Wq    = (const float*)d_in[11];
    const float* bq    = (const float*)d_in[12];
    const float* Wk    = (const float*)d_in[13];
    const float* bk    = (const float*)d_in[14];
    const float* Wv    = (const float*)d_in[15];
    const float* bv    = (const float*)d_in[16];
    const float* Wo    = (const float*)d_in[17];
    const float* bo    = (const float*)d_in[18];
    const float* W1    = (const float*)d_in[19];
    const float* b1    = (const float*)d_in[20];
    const float* W2    = (const float*)d_in[21];
    const float* b2    = (const float*)d_in[22];
    const float* ln1s  = (const float*)d_in[23];
    const float* ln1b  = (const float*)d_in[24];
    const float* ln2s  = (const float*)d_in[25];
    const float* ln2b  = (const float*)d_in[26];
    float* out = (float*)d_out;

    float *x, *q, *k, *v, *h, *bias, *sc;
    cudaGetSymbolAddress((void**)&x,    g_x);
    cudaGetSymbolAddress((void**)&q,    g_q);
    cudaGetSymbolAddress((void**)&k,    g_k);
    cudaGetSymbolAddress((void**)&v,    g_v);
    cudaGetSymbolAddress((void**)&h,    g_h);
    cudaGetSymbolAddress((void**)&bias, g_bias);
    cudaGetSymbolAddress((void**)&sc,   g_sc);

    embed_k<<<(T_*E_ + 255)/256, 256>>>(nt, nif, ind, outd, nemb, iemb, oemb, x);
    long btot = (long)B_*H_*Nn*Nn;
    bias_k<<<(unsigned)((btot + 255)/256), 256>>>(sp, ab, se, ser, bias);

    const float scaling = 0.20412414523193154f;   // 24^-0.5
    dim3 gE(E_/BN, T_/BM);        // (12, 12)
    dim3 gF1(F_/BN, T_/BM);       // (48, 12)
    dim3 gs(B_*H_, Nn/32, Nn/32); // (128, 12, 12)
    dim3 gpv(B_*H_, Nn/32);       // (128, 12)

    for (int l = 0; l < L_; l++) {
        const float* wq = Wq + (size_t)l*E_*E_;
        const float* wk = Wk + (size_t)l*E_*E_;
        const float* wv = Wv + (size_t)l*E_*E_;
        const float* wo = Wo + (size_t)l*E_*E_;
        const float* w1 = W1 + (size_t)l*E_*F_;
        const float* w2 = W2 + (size_t)l*F_*E_;

        tgemm_k<0><<<gE, 256>>>(x, wq, bq + l*E_, q, T_, E_, E_, scaling);
        tgemm_k<0><<<gE, 256>>>(x, wk, bk + l*E_, k, T_, E_, E_, 1.f);
        tgemm_k<0><<<gE, 256>>>(x, wv, bv + l*E_, v, T_, E_, E_, 1.f);

        scores_k<<<gs, 256>>>(q, k, bias, sc);
        softmax_k<<<B_*H_*Nn, 128>>>(sc, nt);
        pv_k<<<gpv, 256>>>(sc, v, q);                       // q := attention context

        tgemm_k<0><<<gE, 256>>>(q, wo, bo + l*E_, k, T_, E_, E_, 1.f);  // k := O-proj
        ln_k<<<T_, 256>>>(x, k, ln1s + l*E_, ln1b + l*E_, x);

        tgemm_k<1><<<gF1, 256>>>(x, w1, b1 + l*F_, h, T_, E_, F_, 1.f);  // gelu fused
        tgemm_k<0><<<gE, 256>>>(h, w2, b2 + l*E_, q, T_, F_, E_, 1.f);   // q := FFN out

        float* dst = (l == L_-1) ? out : x;
        ln_k<<<T_, 256>>>(x, q, ln2s + l*E_, ln2b + l*E_, dst);
    }
}